// round 1
// baseline (speedup 1.0000x reference)
#include <cuda_runtime.h>

#define N0 20000
#define E0 200000
#define M0 8000
#define E1 80000
#define M1 2000
#define E2 20000
#define M2 500
#define BB 64
#define HH 8
#define EPSV 1e-8f

// ---------------- device scratch (no allocs allowed) ----------------
__device__ float g_xT[N0 * BB];            // x transposed: [node][b]
__device__ float g_dataA[M0 * BB * HH];    // layer-0 output: [node][b][h]
__device__ float g_dataB[M1 * BB * HH];    // layer-1 output
__device__ float g_dataC[M2 * BB * HH];    // layer-2 output
__device__ int   g_cnt[M0 + 1];
__device__ int   g_off[M0 + 1];
__device__ int   g_srcl[E0];               // src node id, grouped by dst (CSR)

// ---------------- transpose x[64][20000] -> xT[20000][64] ----------------
__global__ void k_transpose(const float* __restrict__ x) {
    __shared__ float tile[32][33];
    int n0 = blockIdx.x * 32, b0 = blockIdx.y * 32;
    int tx = threadIdx.x, ty0 = threadIdx.y;
#pragma unroll
    for (int i = 0; i < 32; i += 8) {
        int ty = ty0 + i;
        int n = n0 + tx, b = b0 + ty;
        if (n < N0 && b < BB) tile[ty][tx] = x[(size_t)b * N0 + n];
    }
    __syncthreads();
#pragma unroll
    for (int i = 0; i < 32; i += 8) {
        int ty = ty0 + i;
        int n = n0 + ty, b = b0 + tx;
        if (n < N0 && b < BB) g_xT[(size_t)n * BB + b] = tile[tx][ty];
    }
}

// ---------------- CSR build ----------------
__global__ void k_zero(int m) {
    for (int i = blockIdx.x * blockDim.x + threadIdx.x; i <= m;
         i += gridDim.x * blockDim.x)
        g_cnt[i] = 0;
}

__global__ void k_count(const int* __restrict__ dst, int e) {
    for (int i = blockIdx.x * blockDim.x + threadIdx.x; i < e;
         i += gridDim.x * blockDim.x)
        atomicAdd(&g_cnt[dst[i]], 1);
}

// single-block exclusive scan of g_cnt[0..m) -> g_off[0..m]
__global__ void k_scan(int m) {
    __shared__ int s[1024];
    int tid = threadIdx.x;
    int per = (m + 1023) >> 10;
    int base = tid * per;
    int loc = 0;
    for (int i = 0; i < per; i++) {
        int idx = base + i;
        if (idx < m) loc += g_cnt[idx];
    }
    s[tid] = loc;
    __syncthreads();
    int val = loc;
    for (int d = 1; d < 1024; d <<= 1) {
        int t = 0;
        if (tid >= d) t = s[tid - d];
        __syncthreads();
        if (tid >= d) val += t;
        s[tid] = val;
        __syncthreads();
    }
    int ex = val - loc;  // exclusive prefix for this thread's chunk
    for (int i = 0; i < per; i++) {
        int idx = base + i;
        if (idx < m) {
            g_off[idx] = ex;
            ex += g_cnt[idx];
        }
    }
    if (tid == 1023) g_off[m] = val;  // total
}

__global__ void k_fill(const int* __restrict__ src, const int* __restrict__ dst,
                       int e) {
    for (int i = blockIdx.x * blockDim.x + threadIdx.x; i < e;
         i += gridDim.x * blockDim.x) {
        int d = dst[i];
        int p = g_off[d] + atomicAdd(&g_cnt[d], 1);
        g_srcl[p] = src[i];
    }
}

// ---------------- layer 0: aggregate raw x, then *W0, minmax, relu ----------------
// grid = M0 blocks, 256 threads; 16 edge-slots x 16 lanes (float4 over 64 b)
__global__ void k_layer0(const float* __restrict__ W0) {
    int j = blockIdx.x;
    int tid = threadIdx.x;
    int lane = tid & 15, q = tid >> 4;
    int beg = g_off[j], end = g_off[j + 1];

    float4 acc = make_float4(0.f, 0.f, 0.f, 0.f);
    for (int k = beg + q; k < end; k += 16) {
        const float4* row = (const float4*)(g_xT + ((size_t)g_srcl[k] << 6));
        float4 v = row[lane];
        acc.x += v.x; acc.y += v.y; acc.z += v.z; acc.w += v.w;
    }

    __shared__ float4 s4[16][16];
    __shared__ float sMn[2][8], sMx[2][8];
    __shared__ float sOut[512];
    s4[q][lane] = acc;
    __syncthreads();
    for (int s = 8; s; s >>= 1) {
        if (q < s) {
            float4 o = s4[q + s][lane];
            float4 a = s4[q][lane];
            a.x += o.x; a.y += o.y; a.z += o.z; a.w += o.w;
            s4[q][lane] = a;
        }
        __syncthreads();
    }
    const float* sA = (const float*)&s4[0][0];  // sA[b], b = 0..63

    float t[8];
    if (tid < 64) {
        int deg = end - beg;
        float inv = 1.f / (float)(deg > 0 ? deg : 1);
        float a = sA[tid] * inv;
        float mn[8], mx[8];
#pragma unroll
        for (int h = 0; h < 8; h++) {
            t[h] = a * W0[h];
            mn[h] = t[h];
            mx[h] = t[h];
        }
#pragma unroll
        for (int o = 16; o; o >>= 1) {
#pragma unroll
            for (int h = 0; h < 8; h++) {
                mn[h] = fminf(mn[h], __shfl_xor_sync(0xffffffffu, mn[h], o));
                mx[h] = fmaxf(mx[h], __shfl_xor_sync(0xffffffffu, mx[h], o));
            }
        }
        if ((tid & 31) == 0) {
            int w = tid >> 5;
#pragma unroll
            for (int h = 0; h < 8; h++) {
                sMn[w][h] = mn[h];
                sMx[w][h] = mx[h];
            }
        }
    }
    __syncthreads();
    if (tid < 64) {
#pragma unroll
        for (int h = 0; h < 8; h++) {
            float mnF = fminf(sMn[0][h], sMn[1][h]);
            float mxF = fmaxf(sMx[0][h], sMx[1][h]);
            float v = (t[h] - mnF) / (mxF - mnF + EPSV);
            sOut[tid * 8 + h] = fmaxf(v, 0.f);
        }
    }
    __syncthreads();
    if (tid < 128)
        ((float4*)(g_dataA + ((size_t)j << 9)))[tid] =
            ((const float4*)sOut)[tid];
}

// ---------------- layers 1/2: aggregate data rows, 8x8 transform, minmax, relu ----------------
// grid = m blocks, 128 threads; each thread owns one float4 of the 512-f row
__global__ void k_layer12(int layer, const float* __restrict__ W) {
    const float* __restrict__ din = (layer == 1) ? g_dataA : g_dataB;
    float* __restrict__ dout = (layer == 1) ? g_dataB : g_dataC;
    int j = blockIdx.x, tid = threadIdx.x;
    int beg = g_off[j], end = g_off[j + 1];

    float4 acc = make_float4(0.f, 0.f, 0.f, 0.f);
    int k = beg;
    for (; k + 3 < end; k += 4) {
        int a0 = g_srcl[k], a1 = g_srcl[k + 1], a2 = g_srcl[k + 2],
            a3 = g_srcl[k + 3];
        float4 v0 = ((const float4*)(din + ((size_t)a0 << 9)))[tid];
        float4 v1 = ((const float4*)(din + ((size_t)a1 << 9)))[tid];
        float4 v2 = ((const float4*)(din + ((size_t)a2 << 9)))[tid];
        float4 v3 = ((const float4*)(din + ((size_t)a3 << 9)))[tid];
        acc.x += v0.x + v1.x + v2.x + v3.x;
        acc.y += v0.y + v1.y + v2.y + v3.y;
        acc.z += v0.z + v1.z + v2.z + v3.z;
        acc.w += v0.w + v1.w + v2.w + v3.w;
    }
    for (; k < end; k++) {
        float4 v = ((const float4*)(din + ((size_t)g_srcl[k] << 9)))[tid];
        acc.x += v.x; acc.y += v.y; acc.z += v.z; acc.w += v.w;
    }
    int deg = end - beg;
    float inv = 1.f / (float)(deg > 0 ? deg : 1);
    acc.x *= inv; acc.y *= inv; acc.z *= inv; acc.w *= inv;

    __shared__ float sA[512];
    __shared__ float sW[64];
    __shared__ float sMn[2][8], sMx[2][8];
    ((float4*)sA)[tid] = acc;
    if (tid < 64) sW[tid] = W[tid];
    __syncthreads();

    float t[8];
    if (tid < 64) {
        float a[8];
#pragma unroll
        for (int d = 0; d < 8; d++) a[d] = sA[tid * 8 + d];
        float mn[8], mx[8];
#pragma unroll
        for (int h = 0; h < 8; h++) {
            float s = 0.f;
#pragma unroll
            for (int d = 0; d < 8; d++) s += a[d] * sW[h * 8 + d];
            t[h] = s;
            mn[h] = s;
            mx[h] = s;
        }
#pragma unroll
        for (int o = 16; o; o >>= 1) {
#pragma unroll
            for (int h = 0; h < 8; h++) {
                mn[h] = fminf(mn[h], __shfl_xor_sync(0xffffffffu, mn[h], o));
                mx[h] = fmaxf(mx[h], __shfl_xor_sync(0xffffffffu, mx[h], o));
            }
        }
        if ((tid & 31) == 0) {
            int w = tid >> 5;
#pragma unroll
            for (int h = 0; h < 8; h++) {
                sMn[w][h] = mn[h];
                sMx[w][h] = mx[h];
            }
        }
    }
    __syncthreads();
    if (tid < 64) {
#pragma unroll
        for (int h = 0; h < 8; h++) {
            float mnF = fminf(sMn[0][h], sMn[1][h]);
            float mxF = fmaxf(sMx[0][h], sMx[1][h]);
            float v = (t[h] - mnF) / (mxF - mnF + EPSV);
            sA[tid * 8 + h] = fmaxf(v, 0.f);  // reuse sA as output staging
        }
    }
    __syncthreads();
    ((float4*)(dout + ((size_t)j << 9)))[tid] = ((const float4*)sA)[tid];
}

// ---------------- final dot: out[b] = data3[b].flat . Wout + bout ----------------
__global__ void k_out(const float* __restrict__ Wout,
                      const float* __restrict__ bout, float* __restrict__ out) {
    int b = blockIdx.x, tid = threadIdx.x;  // 256 threads
    float acc = 0.f;
    for (int idx = tid; idx < M2 * HH; idx += 256) {
        int j = idx >> 3, h = idx & 7;
        acc += g_dataC[((size_t)j << 9) + b * 8 + h] * Wout[idx];
    }
    __shared__ float s[256];
    s[tid] = acc;
    __syncthreads();
    for (int o = 128; o; o >>= 1) {
        if (tid < o) s[tid] += s[tid + o];
        __syncthreads();
    }
    if (tid == 0) out[b] = s[0] + bout[0];
}

// ---------------- host ----------------
extern "C" void kernel_launch(void* const* d_in, const int* in_sizes, int n_in,
                              void* d_out, int out_size) {
    const float *x = 0, *W0 = 0, *W1 = 0, *W2 = 0, *Wout = 0, *bout = 0;
    const int *s0 = 0, *d0 = 0, *s1 = 0, *d1 = 0, *s2 = 0, *d2 = 0;
    for (int i = 0; i < n_in; i++) {
        int sz = in_sizes[i];
        const void* p = d_in[i];
        if (sz == BB * N0) x = (const float*)p;
        else if (sz == E0) { if (!s0) s0 = (const int*)p; else d0 = (const int*)p; }
        else if (sz == E1) { if (!s1) s1 = (const int*)p; else d1 = (const int*)p; }
        else if (sz == E2) { if (!s2) s2 = (const int*)p; else d2 = (const int*)p; }
        else if (sz == HH) W0 = (const float*)p;
        else if (sz == HH * HH) { if (!W1) W1 = (const float*)p; else W2 = (const float*)p; }
        else if (sz == M2 * HH) Wout = (const float*)p;
        else if (sz == 1) bout = (const float*)p;
    }
    float* out = (float*)d_out;

    k_transpose<<<dim3(N0 / 32, BB / 32), dim3(32, 8)>>>(x);

    // ----- layer 0 -----
    k_zero<<<8, 1024>>>(M0);
    k_count<<<256, 256>>>(d0, E0);
    k_scan<<<1, 1024>>>(M0);
    k_zero<<<8, 1024>>>(M0);
    k_fill<<<256, 256>>>(s0, d0, E0);
    k_layer0<<<M0, 256>>>(W0);

    // ----- layer 1 -----
    k_zero<<<2, 1024>>>(M1);
    k_count<<<128, 256>>>(d1, E1);
    k_scan<<<1, 1024>>>(M1);
    k_zero<<<2, 1024>>>(M1);
    k_fill<<<128, 256>>>(s1, d1, E1);
    k_layer12<<<M1, 128>>>(1, W1);

    // ----- layer 2 -----
    k_zero<<<1, 1024>>>(M2);
    k_count<<<32, 256>>>(d2, E2);
    k_scan<<<1, 1024>>>(M2);
    k_zero<<<1, 1024>>>(M2);
    k_fill<<<32, 256>>>(s2, d2, E2);
    k_layer12<<<M2, 128>>>(2, W2);

    k_out<<<BB, 256>>>(Wout, bout, out);
}

// round 6
// speedup vs baseline: 1.2364x; 1.2364x over previous
#include <cuda_runtime.h>
#include <cuda_fp16.h>

#define N0 20000
#define E0 200000
#define M0 8000
#define E1 80000
#define M1 2000
#define E2 20000
#define M2 500
#define BB 64
#define HH 8
#define EPSV 1e-8f

#define ETOT (E0 + E1 + E2)
#define TP_BLOCKS 1250  /* (20000/32) * (64/32) transpose tiles */

// ---------------- device scratch (no allocs allowed) ----------------
__device__ __half g_xTh[N0 * BB];           // x transposed, fp16: [node][b]
__device__ __half g_dataAh[M0 * BB * HH];   // layer-0 output, fp16: [node][b][h]
__device__ float g_dataB[M1 * BB * HH];     // layer-1 output, fp32
__device__ float g_dataC[M2 * BB * HH];     // layer-2 output, fp32
__device__ int g_cnt0[M0], g_off0[M0 + 1];
__device__ int g_cnt1[M1], g_off1[M1 + 1];
__device__ int g_cnt2[M2], g_off2[M2 + 1];
__device__ int g_src0[E0], g_src1[E1], g_src2[E2];

// ---------------- zero all three count arrays ----------------
__global__ void k_zero_all() {
    int i = blockIdx.x * blockDim.x + threadIdx.x;
    int st = gridDim.x * blockDim.x;
    for (int k = i; k < M0; k += st) g_cnt0[k] = 0;
    for (int k = i; k < M1; k += st) g_cnt1[k] = 0;
    for (int k = i; k < M2; k += st) g_cnt2[k] = 0;
}

// ---------------- fused: transpose x (fp32->fp16) + count all layers' dst ----------------
__global__ void k_prep(const float* __restrict__ x, const int* __restrict__ d0,
                       const int* __restrict__ d1, const int* __restrict__ d2) {
    __shared__ float tile[32][33];
    int b = blockIdx.x;
    int tid = threadIdx.x;
    if (b < TP_BLOCKS) {
        int bx = b % 625, by = b / 625;
        int n0 = bx * 32, b0 = by * 32;
        int tx = tid & 31, ty0 = tid >> 5;
#pragma unroll
        for (int i = 0; i < 32; i += 8) {
            int ty = ty0 + i;
            tile[ty][tx] = x[(size_t)(b0 + ty) * N0 + (n0 + tx)];
        }
        __syncthreads();
#pragma unroll
        for (int i = 0; i < 32; i += 8) {
            int ty = ty0 + i;
            g_xTh[(size_t)(n0 + ty) * BB + (b0 + tx)] =
                __float2half(tile[tx][ty]);
        }
    } else {
        int cb = b - TP_BLOCKS;
        int i0 = cb * 256 + tid;
        int st = (gridDim.x - TP_BLOCKS) * 256;
        for (int i = i0; i < ETOT; i += st) {
            if (i < E0) atomicAdd(&g_cnt0[d0[i]], 1);
            else if (i < E0 + E1) atomicAdd(&g_cnt1[d1[i - E0]], 1);
            else atomicAdd(&g_cnt2[d2[i - E0 - E1]], 1);
        }
    }
}

// ---------------- 3 independent scans, one block each (512 thr) ----------------
// writes off[] (row ptrs) and resets cnt[] to exclusive prefix (= fill cursor)
__global__ void k_scan3() {
    int L = blockIdx.x;
    int m = (L == 0) ? M0 : (L == 1) ? M1 : M2;
    int* cnt = (L == 0) ? g_cnt0 : (L == 1) ? g_cnt1 : g_cnt2;
    int* off = (L == 0) ? g_off0 : (L == 1) ? g_off1 : g_off2;

    int tid = threadIdx.x;  // 512
    int chunk = (m + 511) >> 9;
    int base = tid * chunk;
    int loc = 0;
    for (int i = 0; i < chunk; i++) {
        int idx = base + i;
        if (idx < m) loc += cnt[idx];
    }
    int lane = tid & 31, w = tid >> 5;
    int v = loc;
#pragma unroll
    for (int o = 1; o < 32; o <<= 1) {
        int t = __shfl_up_sync(0xffffffffu, v, o);
        if (lane >= o) v += t;
    }
    __shared__ int wsum[16];
    if (lane == 31) wsum[w] = v;
    __syncthreads();
    if (w == 0 && lane < 16) {
        int t = wsum[lane];
        int vv = t;
#pragma unroll
        for (int o = 1; o < 16; o <<= 1) {
            int u = __shfl_up_sync(0xffffu, vv, o);
            if (lane >= o) vv += u;
        }
        wsum[lane] = vv - t;  // exclusive warp offset
    }
    __syncthreads();
    int ex = v - loc + wsum[w];  // exclusive prefix for this thread's chunk
    for (int i = 0; i < chunk; i++) {
        int idx = base + i;
        if (idx < m) {
            int c = cnt[idx];
            off[idx] = ex;
            cnt[idx] = ex;  // becomes fill cursor
            ex += c;
        }
    }
    if (tid == 511) off[m] = ex;
}

// ---------------- fill all three CSR src lists ----------------
__global__ void k_fill_all(const int* __restrict__ s0, const int* __restrict__ d0,
                           const int* __restrict__ s1, const int* __restrict__ d1,
                           const int* __restrict__ s2, const int* __restrict__ d2) {
    int i0 = blockIdx.x * blockDim.x + threadIdx.x;
    int st = gridDim.x * blockDim.x;
    for (int i = i0; i < ETOT; i += st) {
        if (i < E0) {
            int p = atomicAdd(&g_cnt0[d0[i]], 1);
            g_src0[p] = s0[i];
        } else if (i < E0 + E1) {
            int j = i - E0;
            int p = atomicAdd(&g_cnt1[d1[j]], 1);
            g_src1[p] = s1[j];
        } else {
            int j = i - E0 - E1;
            int p = atomicAdd(&g_cnt2[d2[j]], 1);
            g_src2[p] = s2[j];
        }
    }
}

// ---------------- layer 0: aggregate fp16 x rows, *W0, minmax, relu -> fp16 out ----------------
__global__ void k_layer0(const float* __restrict__ W0) {
    int j = blockIdx.x;
    int tid = threadIdx.x;
    int lane = tid & 15, q = tid >> 4;
    int beg = g_off0[j], end = g_off0[j + 1];

    // each lane owns 4 consecutive b-values; row = 64 halfs = 128B = 16 x uint2
    float4 acc = make_float4(0.f, 0.f, 0.f, 0.f);
    for (int k = beg + q; k < end; k += 16) {
        const uint2* row = (const uint2*)(g_xTh + ((size_t)g_src0[k] << 6));
        uint2 v = row[lane];
        __half2 h0 = *(__half2*)&v.x;
        __half2 h1 = *(__half2*)&v.y;
        float2 f0 = __half22float2(h0);
        float2 f1 = __half22float2(h1);
        acc.x += f0.x; acc.y += f0.y; acc.z += f1.x; acc.w += f1.y;
    }

    __shared__ float4 s4[16][16];
    __shared__ float sMn[2][8], sMx[2][8];
    __shared__ float sOut[512];
    s4[q][lane] = acc;
    __syncthreads();
    for (int s = 8; s; s >>= 1) {
        if (q < s) {
            float4 o = s4[q + s][lane];
            float4 a = s4[q][lane];
            a.x += o.x; a.y += o.y; a.z += o.z; a.w += o.w;
            s4[q][lane] = a;
        }
        __syncthreads();
    }
    const float* sA = (const float*)&s4[0][0];  // sA[b], b = 0..63

    float t[8];
    if (tid < 64) {
        int deg = end - beg;
        float inv = 1.f / (float)(deg > 0 ? deg : 1);
        float a = sA[tid] * inv;
        float mn[8], mx[8];
#pragma unroll
        for (int h = 0; h < 8; h++) {
            t[h] = a * W0[h];
            mn[h] = t[h];
            mx[h] = t[h];
        }
#pragma unroll
        for (int o = 16; o; o >>= 1) {
#pragma unroll
            for (int h = 0; h < 8; h++) {
                mn[h] = fminf(mn[h], __shfl_xor_sync(0xffffffffu, mn[h], o));
                mx[h] = fmaxf(mx[h], __shfl_xor_sync(0xffffffffu, mx[h], o));
            }
        }
        if ((tid & 31) == 0) {
            int w = tid >> 5;
#pragma unroll
            for (int h = 0; h < 8; h++) {
                sMn[w][h] = mn[h];
                sMx[w][h] = mx[h];
            }
        }
    }
    __syncthreads();
    if (tid < 64) {
#pragma unroll
        for (int h = 0; h < 8; h++) {
            float mnF = fminf(sMn[0][h], sMn[1][h]);
            float mxF = fmaxf(sMx[0][h], sMx[1][h]);
            float v = (t[h] - mnF) / (mxF - mnF + EPSV);
            sOut[tid * 8 + h] = fmaxf(v, 0.f);
        }
    }
    __syncthreads();
    // store row as fp16: 512 halfs = 1KB; 128 threads x uint2 (4 halfs)
    if (tid < 128) {
        float4 o = ((const float4*)sOut)[tid];
        __half2 h0 = __floats2half2_rn(o.x, o.y);
        __half2 h1 = __floats2half2_rn(o.z, o.w);
        uint2 st;
        st.x = *(unsigned*)&h0;
        st.y = *(unsigned*)&h1;
        ((uint2*)(g_dataAh + ((size_t)j << 9)))[tid] = st;
    }
}

// ---------------- layer 1: gather fp16 dataA rows -> fp32 dataB ----------------
__global__ void k_layer1(const float* __restrict__ W) {
    int j = blockIdx.x, tid = threadIdx.x;  // 128 threads; thread owns 4 flat vals
    int beg = g_off1[j], end = g_off1[j + 1];

    float4 acc = make_float4(0.f, 0.f, 0.f, 0.f);
    int k = beg;
    for (; k + 3 < end; k += 4) {
        int a0 = g_src1[k], a1 = g_src1[k + 1], a2 = g_src1[k + 2],
            a3 = g_src1[k + 3];
        uint2 v0 = ((const uint2*)(g_dataAh + ((size_t)a0 << 9)))[tid];
        uint2 v1 = ((const uint2*)(g_dataAh + ((size_t)a1 << 9)))[tid];
        uint2 v2 = ((const uint2*)(g_dataAh + ((size_t)a2 << 9)))[tid];
        uint2 v3 = ((const uint2*)(g_dataAh + ((size_t)a3 << 9)))[tid];
#pragma unroll
        for (int u = 0; u < 4; u++) {
            uint2 v = (u == 0) ? v0 : (u == 1) ? v1 : (u == 2) ? v2 : v3;
            float2 f0 = __half22float2(*(__half2*)&v.x);
            float2 f1 = __half22float2(*(__half2*)&v.y);
            acc.x += f0.x; acc.y += f0.y; acc.z += f1.x; acc.w += f1.y;
        }
    }
    for (; k < end; k++) {
        uint2 v = ((const uint2*)(g_dataAh + ((size_t)g_src1[k] << 9)))[tid];
        float2 f0 = __half22float2(*(__half2*)&v.x);
        float2 f1 = __half22float2(*(__half2*)&v.y);
        acc.x += f0.x; acc.y += f0.y; acc.z += f1.x; acc.w += f1.y;
    }
    int deg = end - beg;
    float inv = 1.f / (float)(deg > 0 ? deg : 1);
    acc.x *= inv; acc.y *= inv; acc.z *= inv; acc.w *= inv;

    __shared__ float sA[512];
    __shared__ float sW[64];
    __shared__ float sMn[2][8], sMx[2][8];
    ((float4*)sA)[tid] = acc;
    if (tid < 64) sW[tid] = W[tid];
    __syncthreads();

    float t[8];
    if (tid < 64) {
        float a[8];
#pragma unroll
        for (int d = 0; d < 8; d++) a[d] = sA[tid * 8 + d];
        float mn[8], mx[8];
#pragma unroll
        for (int h = 0; h < 8; h++) {
            float s = 0.f;
#pragma unroll
            for (int d = 0; d < 8; d++) s += a[d] * sW[h * 8 + d];
            t[h] = s;
            mn[h] = s;
            mx[h] = s;
        }
#pragma unroll
        for (int o = 16; o; o >>= 1) {
#pragma unroll
            for (int h = 0; h < 8; h++) {
                mn[h] = fminf(mn[h], __shfl_xor_sync(0xffffffffu, mn[h], o));
                mx[h] = fmaxf(mx[h], __shfl_xor_sync(0xffffffffu, mx[h], o));
            }
        }
        if ((tid & 31) == 0) {
            int w = tid >> 5;
#pragma unroll
            for (int h = 0; h < 8; h++) {
                sMn[w][h] = mn[h];
                sMx[w][h] = mx[h];
            }
        }
    }
    __syncthreads();
    if (tid < 64) {
#pragma unroll
        for (int h = 0; h < 8; h++) {
            float mnF = fminf(sMn[0][h], sMn[1][h]);
            float mxF = fmaxf(sMx[0][h], sMx[1][h]);
            float v = (t[h] - mnF) / (mxF - mnF + EPSV);
            sA[tid * 8 + h] = fmaxf(v, 0.f);
        }
    }
    __syncthreads();
    ((float4*)(g_dataB + ((size_t)j << 9)))[tid] = ((const float4*)sA)[tid];
}

// ---------------- layer 2: gather fp32 dataB rows -> fp32 dataC ----------------
__global__ void k_layer2(const float* __restrict__ W) {
    int j = blockIdx.x, tid = threadIdx.x;
    int beg = g_off2[j], end = g_off2[j + 1];

    float4 acc = make_float4(0.f, 0.f, 0.f, 0.f);
    int k = beg;
    for (; k + 3 < end; k += 4) {
        int a0 = g_src2[k], a1 = g_src2[k + 1], a2 = g_src2[k + 2],
            a3 = g_src2[k + 3];
        float4 v0 = ((const float4*)(g_dataB + ((size_t)a0 << 9)))[tid];
        float4 v1 = ((const float4*)(g_dataB + ((size_t)a1 << 9)))[tid];
        float4 v2 = ((const float4*)(g_dataB + ((size_t)a2 << 9)))[tid];
        float4 v3 = ((const float4*)(g_dataB + ((size_t)a3 << 9)))[tid];
        acc.x += v0.x + v1.x + v2.x + v3.x;
        acc.y += v0.y + v1.y + v2.y + v3.y;
        acc.z += v0.z + v1.z + v2.z + v3.z;
        acc.w += v0.w + v1.w + v2.w + v3.w;
    }
    for (; k < end; k++) {
        float4 v = ((const float4*)(g_dataB + ((size_t)g_src2[k] << 9)))[tid];
        acc.x += v.x; acc.y += v.y; acc.z += v.z; acc.w += v.w;
    }
    int deg = end - beg;
    float inv = 1.f / (float)(deg > 0 ? deg : 1);
    acc.x *= inv; acc.y *= inv; acc.z *= inv; acc.w *= inv;

    __shared__ float sA[512];
    __shared__ float sW[64];
    __shared__ float sMn[2][8], sMx[2][8];
    ((float4*)sA)[tid] = acc;
    if (tid < 64) sW[tid] = W[tid];
    __syncthreads();

    float t[8];
    if (tid < 64) {
        float a[8];
#pragma unroll
        for (int d = 0; d < 8; d++) a[d] = sA[tid * 8 + d];
        float mn[8], mx[8];
#pragma unroll
        for (int h = 0; h < 8; h++) {
            float s = 0.f;
#pragma unroll
            for (int d = 0; d < 8; d++) s += a[d] * sW[h * 8 + d];
            t[h] = s;
            mn[h] = s;
            mx[h] = s;
        }
#pragma unroll
        for (int o = 16; o; o >>= 1) {
#pragma unroll
            for (int h = 0; h < 8; h++) {
                mn[h] = fminf(mn[h], __shfl_xor_sync(0xffffffffu, mn[h], o));
                mx[h] = fmaxf(mx[h], __shfl_xor_sync(0xffffffffu, mx[h], o));
            }
        }
        if ((tid & 31) == 0) {
            int w = tid >> 5;
#pragma unroll
            for (int h = 0; h < 8; h++) {
                sMn[w][h] = mn[h];
                sMx[w][h] = mx[h];
            }
        }
    }
    __syncthreads();
    if (tid < 64) {
#pragma unroll
        for (int h = 0; h < 8; h++) {
            float mnF = fminf(sMn[0][h], sMn[1][h]);
            float mxF = fmaxf(sMx[0][h], sMx[1][h]);
            float v = (t[h] - mnF) / (mxF - mnF + EPSV);
            sA[tid * 8 + h] = fmaxf(v, 0.f);
        }
    }
    __syncthreads();
    ((float4*)(g_dataC + ((size_t)j << 9)))[tid] = ((const float4*)sA)[tid];
}

// ---------------- final dot: out[b] = data3[b].flat . Wout + bout ----------------
__global__ void k_out(const float* __restrict__ Wout,
                      const float* __restrict__ bout, float* __restrict__ out) {
    int b = blockIdx.x, tid = threadIdx.x;  // 256 threads
    float acc = 0.f;
    for (int idx = tid; idx < M2 * HH; idx += 256) {
        int j = idx >> 3, h = idx & 7;
        acc += g_dataC[((size_t)j << 9) + b * 8 + h] * Wout[idx];
    }
    __shared__ float s[256];
    s[tid] = acc;
    __syncthreads();
    for (int o = 128; o; o >>= 1) {
        if (tid < o) s[tid] += s[tid + o];
        __syncthreads();
    }
    if (tid == 0) out[b] = s[0] + bout[0];
}

// ---------------- host ----------------
extern "C" void kernel_launch(void* const* d_in, const int* in_sizes, int n_in,
                              void* d_out, int out_size) {
    const float *x = 0, *W0 = 0, *W1 = 0, *W2 = 0, *Wout = 0, *bout = 0;
    const int *s0 = 0, *d0 = 0, *s1 = 0, *d1 = 0, *s2 = 0, *d2 = 0;
    for (int i = 0; i < n_in; i++) {
        int sz = in_sizes[i];
        const void* p = d_in[i];
        if (sz == BB * N0) x = (const float*)p;
        else if (sz == E0) { if (!s0) s0 = (const int*)p; else d0 = (const int*)p; }
        else if (sz == E1) { if (!s1) s1 = (const int*)p; else d1 = (const int*)p; }
        else if (sz == E2) { if (!s2) s2 = (const int*)p; else d2 = (const int*)p; }
        else if (sz == HH) W0 = (const float*)p;
        else if (sz == HH * HH) { if (!W1) W1 = (const float*)p; else W2 = (const float*)p; }
        else if (sz == M2 * HH) Wout = (const float*)p;
        else if (sz == 1) bout = (const float*)p;
    }
    float* out = (float*)d_out;

    k_zero_all<<<42, 256>>>();
    k_prep<<<TP_BLOCKS + 300, 256>>>(x, d0, d1, d2);
    k_scan3<<<3, 512>>>();
    k_fill_all<<<256, 256>>>(s0, d0, s1, d1, s2, d2);
    k_layer0<<<M0, 256>>>(W0);
    k_layer1<<<M1, 128>>>(W1);
    k_layer2<<<M2, 128>>>(W2);
    k_out<<<BB, 256>>>(Wout, bout, out);
}

// round 7
// speedup vs baseline: 1.5328x; 1.2397x over previous
#include <cuda_runtime.h>
#include <cuda_fp16.h>

#define N0 20000
#define E0 200000
#define M0 8000
#define E1 80000
#define M1 2000
#define E2 20000
#define M2 500
#define BB 64
#define HH 8
#define EPSV 1e-8f

#define ETOT (E0 + E1 + E2)
#define TP_BLOCKS 1250  /* (20000/32) * (64/32) transpose tiles */
#define EB ((ETOT + 255) / 256)  /* one-edge-per-thread blocks = 1172 */
#define MAXDEG 96

// ---------------- device scratch (no allocs allowed) ----------------
__device__ __half g_xTh[N0 * BB];           // x transposed, fp16: [node][b]
__device__ __half g_dataAh[M0 * BB * HH];   // layer-0 output, fp16
__device__ float g_dataB[M1 * BB * HH];     // layer-1 output, fp32
__device__ float g_dataC[M2 * BB * HH];     // layer-2 output, fp32
__device__ int g_cnt0[M0], g_cnt1[M1], g_cnt2[M2];
__device__ int g_ell0[M0 * MAXDEG];
__device__ int g_ell1[M1 * MAXDEG];
__device__ int g_ell2[M2 * MAXDEG];

// ---------------- zero all three count arrays ----------------
__global__ void k_zero_all() {
    int i = blockIdx.x * blockDim.x + threadIdx.x;
    int st = gridDim.x * blockDim.x;
    for (int k = i; k < M0; k += st) g_cnt0[k] = 0;
    for (int k = i; k < M1; k += st) g_cnt1[k] = 0;
    for (int k = i; k < M2; k += st) g_cnt2[k] = 0;
}

// ---------------- fused: transpose x (fp32->fp16) + one-pass ELL fill ----------------
__global__ void k_prep(const float* __restrict__ x,
                       const int* __restrict__ s0, const int* __restrict__ d0,
                       const int* __restrict__ s1, const int* __restrict__ d1,
                       const int* __restrict__ s2, const int* __restrict__ d2) {
    int b = blockIdx.x;
    int tid = threadIdx.x;
    if (b < TP_BLOCKS) {
        __shared__ float tile[32][33];
        int bx = b % 625, by = b / 625;
        int n0 = bx * 32, b0 = by * 32;
        int tx = tid & 31, ty0 = tid >> 5;
#pragma unroll
        for (int i = 0; i < 32; i += 8) {
            int ty = ty0 + i;
            tile[ty][tx] = x[(size_t)(b0 + ty) * N0 + (n0 + tx)];
        }
        __syncthreads();
#pragma unroll
        for (int i = 0; i < 32; i += 8) {
            int ty = ty0 + i;
            g_xTh[(size_t)(n0 + ty) * BB + (b0 + tx)] =
                __float2half(tile[tx][ty]);
        }
    } else {
        // one edge per thread: load dst, grab slot, scatter src
        int i = (b - TP_BLOCKS) * 256 + tid;
        if (i < E0) {
            int d = d0[i];
            int slot = atomicAdd(&g_cnt0[d], 1);
            g_ell0[d * MAXDEG + slot] = s0[i];
        } else if (i < E0 + E1) {
            int j = i - E0;
            int d = d1[j];
            int slot = atomicAdd(&g_cnt1[d], 1);
            g_ell1[d * MAXDEG + slot] = s1[j];
        } else if (i < ETOT) {
            int j = i - E0 - E1;
            int d = d2[j];
            int slot = atomicAdd(&g_cnt2[d], 1);
            g_ell2[d * MAXDEG + slot] = s2[j];
        }
    }
}

// ---------------- layer 0: aggregate fp16 x rows, *W0, minmax, relu -> fp16 out ----------------
__global__ void k_layer0(const float* __restrict__ W0) {
    int j = blockIdx.x;
    int tid = threadIdx.x;
    int lane = tid & 15, q = tid >> 4;
    int deg = g_cnt0[j];
    const int* __restrict__ row_ids = g_ell0 + j * MAXDEG;

    // each lane owns 4 consecutive b-values; row = 64 halfs = 128B = 16 x uint2
    float4 acc = make_float4(0.f, 0.f, 0.f, 0.f);
    for (int k = q; k < deg; k += 16) {
        const uint2* row = (const uint2*)(g_xTh + ((size_t)row_ids[k] << 6));
        uint2 v = row[lane];
        float2 f0 = __half22float2(*(__half2*)&v.x);
        float2 f1 = __half22float2(*(__half2*)&v.y);
        acc.x += f0.x; acc.y += f0.y; acc.z += f1.x; acc.w += f1.y;
    }

    __shared__ float4 s4[16][16];
    __shared__ float sMn[2][8], sMx[2][8];
    __shared__ float sOut[512];
    s4[q][lane] = acc;
    __syncthreads();
    for (int s = 8; s; s >>= 1) {
        if (q < s) {
            float4 o = s4[q + s][lane];
            float4 a = s4[q][lane];
            a.x += o.x; a.y += o.y; a.z += o.z; a.w += o.w;
            s4[q][lane] = a;
        }
        __syncthreads();
    }
    const float* sA = (const float*)&s4[0][0];  // sA[b], b = 0..63

    float t[8];
    if (tid < 64) {
        float inv = 1.f / (float)(deg > 0 ? deg : 1);
        float a = sA[tid] * inv;
        float mn[8], mx[8];
#pragma unroll
        for (int h = 0; h < 8; h++) {
            t[h] = a * W0[h];
            mn[h] = t[h];
            mx[h] = t[h];
        }
#pragma unroll
        for (int o = 16; o; o >>= 1) {
#pragma unroll
            for (int h = 0; h < 8; h++) {
                mn[h] = fminf(mn[h], __shfl_xor_sync(0xffffffffu, mn[h], o));
                mx[h] = fmaxf(mx[h], __shfl_xor_sync(0xffffffffu, mx[h], o));
            }
        }
        if ((tid & 31) == 0) {
            int w = tid >> 5;
#pragma unroll
            for (int h = 0; h < 8; h++) {
                sMn[w][h] = mn[h];
                sMx[w][h] = mx[h];
            }
        }
    }
    __syncthreads();
    if (tid < 64) {
#pragma unroll
        for (int h = 0; h < 8; h++) {
            float mnF = fminf(sMn[0][h], sMn[1][h]);
            float mxF = fmaxf(sMx[0][h], sMx[1][h]);
            float v = (t[h] - mnF) / (mxF - mnF + EPSV);
            sOut[tid * 8 + h] = fmaxf(v, 0.f);
        }
    }
    __syncthreads();
    // store row as fp16: 512 halfs = 1KB; 128 threads x uint2 (4 halfs)
    if (tid < 128) {
        float4 o = ((const float4*)sOut)[tid];
        __half2 h0 = __floats2half2_rn(o.x, o.y);
        __half2 h1 = __floats2half2_rn(o.z, o.w);
        uint2 st;
        st.x = *(unsigned*)&h0;
        st.y = *(unsigned*)&h1;
        ((uint2*)(g_dataAh + ((size_t)j << 9)))[tid] = st;
    }
}

// ---------------- layer 1: gather fp16 dataA rows -> fp32 dataB ----------------
__global__ void k_layer1(const float* __restrict__ W) {
    int j = blockIdx.x, tid = threadIdx.x;  // 128 threads; thread owns 4 flat vals
    int deg = g_cnt1[j];
    const int* __restrict__ row_ids = g_ell1 + j * MAXDEG;

    float4 acc = make_float4(0.f, 0.f, 0.f, 0.f);
    int k = 0;
    for (; k + 3 < deg; k += 4) {
        int a0 = row_ids[k], a1 = row_ids[k + 1], a2 = row_ids[k + 2],
            a3 = row_ids[k + 3];
        uint2 v0 = ((const uint2*)(g_dataAh + ((size_t)a0 << 9)))[tid];
        uint2 v1 = ((const uint2*)(g_dataAh + ((size_t)a1 << 9)))[tid];
        uint2 v2 = ((const uint2*)(g_dataAh + ((size_t)a2 << 9)))[tid];
        uint2 v3 = ((const uint2*)(g_dataAh + ((size_t)a3 << 9)))[tid];
#pragma unroll
        for (int u = 0; u < 4; u++) {
            uint2 v = (u == 0) ? v0 : (u == 1) ? v1 : (u == 2) ? v2 : v3;
            float2 f0 = __half22float2(*(__half2*)&v.x);
            float2 f1 = __half22float2(*(__half2*)&v.y);
            acc.x += f0.x; acc.y += f0.y; acc.z += f1.x; acc.w += f1.y;
        }
    }
    for (; k < deg; k++) {
        uint2 v = ((const uint2*)(g_dataAh + ((size_t)row_ids[k] << 9)))[tid];
        float2 f0 = __half22float2(*(__half2*)&v.x);
        float2 f1 = __half22float2(*(__half2*)&v.y);
        acc.x += f0.x; acc.y += f0.y; acc.z += f1.x; acc.w += f1.y;
    }
    float inv = 1.f / (float)(deg > 0 ? deg : 1);
    acc.x *= inv; acc.y *= inv; acc.z *= inv; acc.w *= inv;

    __shared__ float sA[512];
    __shared__ float sW[64];
    __shared__ float sMn[2][8], sMx[2][8];
    ((float4*)sA)[tid] = acc;
    if (tid < 64) sW[tid] = W[tid];
    __syncthreads();

    float t[8];
    if (tid < 64) {
        float a[8];
#pragma unroll
        for (int d = 0; d < 8; d++) a[d] = sA[tid * 8 + d];
        float mn[8], mx[8];
#pragma unroll
        for (int h = 0; h < 8; h++) {
            float s = 0.f;
#pragma unroll
            for (int d = 0; d < 8; d++) s += a[d] * sW[h * 8 + d];
            t[h] = s;
            mn[h] = s;
            mx[h] = s;
        }
#pragma unroll
        for (int o = 16; o; o >>= 1) {
#pragma unroll
            for (int h = 0; h < 8; h++) {
                mn[h] = fminf(mn[h], __shfl_xor_sync(0xffffffffu, mn[h], o));
                mx[h] = fmaxf(mx[h], __shfl_xor_sync(0xffffffffu, mx[h], o));
            }
        }
        if ((tid & 31) == 0) {
            int w = tid >> 5;
#pragma unroll
            for (int h = 0; h < 8; h++) {
                sMn[w][h] = mn[h];
                sMx[w][h] = mx[h];
            }
        }
    }
    __syncthreads();
    if (tid < 64) {
#pragma unroll
        for (int h = 0; h < 8; h++) {
            float mnF = fminf(sMn[0][h], sMn[1][h]);
            float mxF = fmaxf(sMx[0][h], sMx[1][h]);
            float v = (t[h] - mnF) / (mxF - mnF + EPSV);
            sA[tid * 8 + h] = fmaxf(v, 0.f);
        }
    }
    __syncthreads();
    ((float4*)(g_dataB + ((size_t)j << 9)))[tid] = ((const float4*)sA)[tid];
}

// ---------------- layer 2: gather fp32 dataB rows -> fp32 dataC ----------------
__global__ void k_layer2(const float* __restrict__ W) {
    int j = blockIdx.x, tid = threadIdx.x;
    int deg = g_cnt2[j];
    const int* __restrict__ row_ids = g_ell2 + j * MAXDEG;

    float4 acc = make_float4(0.f, 0.f, 0.f, 0.f);
    int k = 0;
    for (; k + 3 < deg; k += 4) {
        int a0 = row_ids[k], a1 = row_ids[k + 1], a2 = row_ids[k + 2],
            a3 = row_ids[k + 3];
        float4 v0 = ((const float4*)(g_dataB + ((size_t)a0 << 9)))[tid];
        float4 v1 = ((const float4*)(g_dataB + ((size_t)a1 << 9)))[tid];
        float4 v2 = ((const float4*)(g_dataB + ((size_t)a2 << 9)))[tid];
        float4 v3 = ((const float4*)(g_dataB + ((size_t)a3 << 9)))[tid];
        acc.x += v0.x + v1.x + v2.x + v3.x;
        acc.y += v0.y + v1.y + v2.y + v3.y;
        acc.z += v0.z + v1.z + v2.z + v3.z;
        acc.w += v0.w + v1.w + v2.w + v3.w;
    }
    for (; k < deg; k++) {
        float4 v = ((const float4*)(g_dataB + ((size_t)row_ids[k] << 9)))[tid];
        acc.x += v.x; acc.y += v.y; acc.z += v.z; acc.w += v.w;
    }
    float inv = 1.f / (float)(deg > 0 ? deg : 1);
    acc.x *= inv; acc.y *= inv; acc.z *= inv; acc.w *= inv;

    __shared__ float sA[512];
    __shared__ float sW[64];
    __shared__ float sMn[2][8], sMx[2][8];
    ((float4*)sA)[tid] = acc;
    if (tid < 64) sW[tid] = W[tid];
    __syncthreads();

    float t[8];
    if (tid < 64) {
        float a[8];
#pragma unroll
        for (int d = 0; d < 8; d++) a[d] = sA[tid * 8 + d];
        float mn[8], mx[8];
#pragma unroll
        for (int h = 0; h < 8; h++) {
            float s = 0.f;
#pragma unroll
            for (int d = 0; d < 8; d++) s += a[d] * sW[h * 8 + d];
            t[h] = s;
            mn[h] = s;
            mx[h] = s;
        }
#pragma unroll
        for (int o = 16; o; o >>= 1) {
#pragma unroll
            for (int h = 0; h < 8; h++) {
                mn[h] = fminf(mn[h], __shfl_xor_sync(0xffffffffu, mn[h], o));
                mx[h] = fmaxf(mx[h], __shfl_xor_sync(0xffffffffu, mx[h], o));
            }
        }
        if ((tid & 31) == 0) {
            int w = tid >> 5;
#pragma unroll
            for (int h = 0; h < 8; h++) {
                sMn[w][h] = mn[h];
                sMx[w][h] = mx[h];
            }
        }
    }
    __syncthreads();
    if (tid < 64) {
#pragma unroll
        for (int h = 0; h < 8; h++) {
            float mnF = fminf(sMn[0][h], sMn[1][h]);
            float mxF = fmaxf(sMx[0][h], sMx[1][h]);
            float v = (t[h] - mnF) / (mxF - mnF + EPSV);
            sA[tid * 8 + h] = fmaxf(v, 0.f);
        }
    }
    __syncthreads();
    ((float4*)(g_dataC + ((size_t)j << 9)))[tid] = ((const float4*)sA)[tid];
}

// ---------------- final dot: out[b] = data3[b].flat . Wout + bout ----------------
__global__ void k_out(const float* __restrict__ Wout,
                      const float* __restrict__ bout, float* __restrict__ out) {
    int b = blockIdx.x, tid = threadIdx.x;  // 256 threads
    float acc = 0.f;
    for (int idx = tid; idx < M2 * HH; idx += 256) {
        int j = idx >> 3, h = idx & 7;
        acc += g_dataC[((size_t)j << 9) + b * 8 + h] * Wout[idx];
    }
    __shared__ float s[256];
    s[tid] = acc;
    __syncthreads();
    for (int o = 128; o; o >>= 1) {
        if (tid < o) s[tid] += s[tid + o];
        __syncthreads();
    }
    if (tid == 0) out[b] = s[0] + bout[0];
}

// ---------------- host ----------------
extern "C" void kernel_launch(void* const* d_in, const int* in_sizes, int n_in,
                              void* d_out, int out_size) {
    const float *x = 0, *W0 = 0, *W1 = 0, *W2 = 0, *Wout = 0, *bout = 0;
    const int *s0 = 0, *d0 = 0, *s1 = 0, *d1 = 0, *s2 = 0, *d2 = 0;
    for (int i = 0; i < n_in; i++) {
        int sz = in_sizes[i];
        const void* p = d_in[i];
        if (sz == BB * N0) x = (const float*)p;
        else if (sz == E0) { if (!s0) s0 = (const int*)p; else d0 = (const int*)p; }
        else if (sz == E1) { if (!s1) s1 = (const int*)p; else d1 = (const int*)p; }
        else if (sz == E2) { if (!s2) s2 = (const int*)p; else d2 = (const int*)p; }
        else if (sz == HH) W0 = (const float*)p;
        else if (sz == HH * HH) { if (!W1) W1 = (const float*)p; else W2 = (const float*)p; }
        else if (sz == M2 * HH) Wout = (const float*)p;
        else if (sz == 1) bout = (const float*)p;
    }
    float* out = (float*)d_out;

    k_zero_all<<<42, 256>>>();
    k_prep<<<TP_BLOCKS + EB + 1, 256>>>(x, s0, d0, s1, d1, s2, d2);
    k_layer0<<<M0, 256>>>(W0);
    k_layer1<<<M1, 128>>>(W1);
    k_layer2<<<M2, 128>>>(W2);
    k_out<<<BB, 256>>>(Wout, bout, out);
}

// round 9
// speedup vs baseline: 1.5560x; 1.0151x over previous
#include <cuda_runtime.h>
#include <cuda_fp16.h>

#define N0 20000
#define E0 200000
#define M0 8000
#define E1 80000
#define M1 2000
#define E2 20000
#define M2 500
#define BB 64
#define HH 8
#define EPSV 1e-8f

#define ETOT (E0 + E1 + E2)
#define TP_BLOCKS 1250  /* (20000/32) * (64/32) transpose tiles */
#define EB ((ETOT + 255) / 256)  /* one-edge-per-thread blocks */
#define MAXDEG 96

// ---------------- device scratch (no allocs allowed) ----------------
__device__ __half g_xTh[N0 * BB];           // x transposed, fp16: [node][b]
__device__ __half g_dataAh[M0 * BB * HH];   // layer-0 output, fp16
__device__ float g_dataB[M1 * BB * HH];     // layer-1 output, fp32
__device__ float g_dataC[M2 * BB * HH];     // layer-2 output, fp32
__device__ int g_cnt0[M0], g_cnt1[M1], g_cnt2[M2];
__device__ int g_ell0[M0 * MAXDEG];
__device__ int g_ell1[M1 * MAXDEG];
__device__ int g_ell2[M2 * MAXDEG];

__device__ __forceinline__ void acc8_from_uint4(float* acc, uint4 v) {
    float2 f0 = __half22float2(*(__half2*)&v.x);
    float2 f1 = __half22float2(*(__half2*)&v.y);
    float2 f2 = __half22float2(*(__half2*)&v.z);
    float2 f3 = __half22float2(*(__half2*)&v.w);
    acc[0] += f0.x; acc[1] += f0.y; acc[2] += f1.x; acc[3] += f1.y;
    acc[4] += f2.x; acc[5] += f2.y; acc[6] += f3.x; acc[7] += f3.y;
}

// ---------------- zero all three count arrays ----------------
__global__ void k_zero_all() {
    int i = blockIdx.x * blockDim.x + threadIdx.x;
    int st = gridDim.x * blockDim.x;
    for (int k = i; k < M0; k += st) g_cnt0[k] = 0;
    for (int k = i; k < M1; k += st) g_cnt1[k] = 0;
    for (int k = i; k < M2; k += st) g_cnt2[k] = 0;
}

// ---------------- fused: transpose x (fp32->fp16) + one-pass ELL fill ----------------
__global__ void k_prep(const float* __restrict__ x,
                       const int* __restrict__ s0, const int* __restrict__ d0,
                       const int* __restrict__ s1, const int* __restrict__ d1,
                       const int* __restrict__ s2, const int* __restrict__ d2) {
    int b = blockIdx.x;
    int tid = threadIdx.x;
    if (b < TP_BLOCKS) {
        __shared__ float tile[32][33];
        int bx = b % 625, by = b / 625;
        int n0 = bx * 32, b0 = by * 32;
        int tx = tid & 31, ty0 = tid >> 5;
#pragma unroll
        for (int i = 0; i < 32; i += 8) {
            int ty = ty0 + i;
            tile[ty][tx] = x[(size_t)(b0 + ty) * N0 + (n0 + tx)];
        }
        __syncthreads();
#pragma unroll
        for (int i = 0; i < 32; i += 8) {
            int ty = ty0 + i;
            g_xTh[(size_t)(n0 + ty) * BB + (b0 + tx)] =
                __float2half(tile[tx][ty]);
        }
    } else {
        // one edge per thread: load dst, grab slot, scatter src
        int i = (b - TP_BLOCKS) * 256 + tid;
        if (i < E0) {
            int d = d0[i];
            int slot = atomicAdd(&g_cnt0[d], 1);
            g_ell0[d * MAXDEG + slot] = s0[i];
        } else if (i < E0 + E1) {
            int j = i - E0;
            int d = d1[j];
            int slot = atomicAdd(&g_cnt1[d], 1);
            g_ell1[d * MAXDEG + slot] = s1[j];
        } else if (i < ETOT) {
            int j = i - E0 - E1;
            int d = d2[j];
            int slot = atomicAdd(&g_cnt2[d], 1);
            g_ell2[d * MAXDEG + slot] = s2[j];
        }
    }
}

// ---------------- layer 0: 256 thr; 8 lanes(uint4) x 32 edge-groups ----------------
__global__ void k_layer0(const float* __restrict__ W0) {
    int j = blockIdx.x;
    int tid = threadIdx.x;
    int lane = tid & 7, grp = tid >> 3;  // lane: 16B chunk (8 b-vals), grp: edge slot
    int deg = g_cnt0[j];
    const int* __restrict__ row_ids = g_ell0 + j * MAXDEG;

    float acc[8];
#pragma unroll
    for (int i = 0; i < 8; i++) acc[i] = 0.f;
    for (int k = grp; k < deg; k += 32) {
        const uint4* row = (const uint4*)(g_xTh + ((size_t)row_ids[k] << 6));
        acc8_from_uint4(acc, row[lane]);
    }

    __shared__ float sP[32][64];  // [group][b]
    __shared__ float sMn[2][8], sMx[2][8];
#pragma unroll
    for (int i = 0; i < 8; i++) sP[grp][lane * 8 + i] = acc[i];
    __syncthreads();

    float t[8];
    if (tid < 64) {
        // sum 32 groups for b = tid
        float a = 0.f;
#pragma unroll
        for (int g = 0; g < 32; g++) a += sP[g][tid];
        float inv = 1.f / (float)(deg > 0 ? deg : 1);
        a *= inv;
        float mn[8], mx[8];
#pragma unroll
        for (int h = 0; h < 8; h++) {
            t[h] = a * W0[h];
            mn[h] = t[h];
            mx[h] = t[h];
        }
#pragma unroll
        for (int o = 16; o; o >>= 1) {
#pragma unroll
            for (int h = 0; h < 8; h++) {
                mn[h] = fminf(mn[h], __shfl_xor_sync(0xffffffffu, mn[h], o));
                mx[h] = fmaxf(mx[h], __shfl_xor_sync(0xffffffffu, mx[h], o));
            }
        }
        if ((tid & 31) == 0) {
            int w = tid >> 5;
#pragma unroll
            for (int h = 0; h < 8; h++) {
                sMn[w][h] = mn[h];
                sMx[w][h] = mx[h];
            }
        }
    }
    __syncthreads();
    float* sOut = &sP[0][0];  // reuse as 512-float staging
    if (tid < 64) {
#pragma unroll
        for (int h = 0; h < 8; h++) {
            float mnF = fminf(sMn[0][h], sMn[1][h]);
            float mxF = fmaxf(sMx[0][h], sMx[1][h]);
            float v = (t[h] - mnF) / (mxF - mnF + EPSV);
            sOut[tid * 8 + h] = fmaxf(v, 0.f);
        }
    }
    __syncthreads();
    // store row as fp16: 512 halfs = 1KB; 128 threads x uint2 (4 halfs)
    if (tid < 128) {
        float4 o = ((const float4*)sOut)[tid];
        __half2 h0 = __floats2half2_rn(o.x, o.y);
        __half2 h1 = __floats2half2_rn(o.z, o.w);
        uint2 st;
        st.x = *(unsigned*)&h0;
        st.y = *(unsigned*)&h1;
        ((uint2*)(g_dataAh + ((size_t)j << 9)))[tid] = st;
    }
}

// ---------------- layer 1: 128 thr; 64 lanes(uint4) x 2 edge-groups, unroll 4 ----------------
__global__ void k_layer1(const float* __restrict__ W) {
    int j = blockIdx.x, tid = threadIdx.x;
    int lane = tid & 63, grp = tid >> 6;  // lane: 16B chunk of 1KB row, grp: 0/1
    int deg = g_cnt1[j];
    const int* __restrict__ row_ids = g_ell1 + j * MAXDEG;

    float acc[8];
#pragma unroll
    for (int i = 0; i < 8; i++) acc[i] = 0.f;
    int k = grp;
    for (; k + 6 < deg; k += 8) {  // edges k, k+2, k+4, k+6 (stride 2 within group)
        uint4 v0 = ((const uint4*)(g_dataAh + ((size_t)row_ids[k] << 9)))[lane];
        uint4 v1 = ((const uint4*)(g_dataAh + ((size_t)row_ids[k + 2] << 9)))[lane];
        uint4 v2 = ((const uint4*)(g_dataAh + ((size_t)row_ids[k + 4] << 9)))[lane];
        uint4 v3 = ((const uint4*)(g_dataAh + ((size_t)row_ids[k + 6] << 9)))[lane];
        acc8_from_uint4(acc, v0);
        acc8_from_uint4(acc, v1);
        acc8_from_uint4(acc, v2);
        acc8_from_uint4(acc, v3);
    }
    for (; k < deg; k += 2) {
        uint4 v = ((const uint4*)(g_dataAh + ((size_t)row_ids[k] << 9)))[lane];
        acc8_from_uint4(acc, v);
    }

    __shared__ float sP[2][64][8];  // [group][b][h]
    __shared__ float sW[64];
    __shared__ float sMn[2][8], sMx[2][8];
#pragma unroll
    for (int i = 0; i < 8; i++) sP[grp][lane][i] = acc[i];
    if (tid < 64) sW[tid] = W[tid];
    __syncthreads();

    float t[8];
    if (tid < 64) {
        float inv = 1.f / (float)(deg > 0 ? deg : 1);
        float a[8];
#pragma unroll
        for (int d = 0; d < 8; d++)
            a[d] = (sP[0][tid][d] + sP[1][tid][d]) * inv;
        float mn[8], mx[8];
#pragma unroll
        for (int h = 0; h < 8; h++) {
            float s = 0.f;
#pragma unroll
            for (int d = 0; d < 8; d++) s += a[d] * sW[h * 8 + d];
            t[h] = s;
            mn[h] = s;
            mx[h] = s;
        }
#pragma unroll
        for (int o = 16; o; o >>= 1) {
#pragma unroll
            for (int h = 0; h < 8; h++) {
                mn[h] = fminf(mn[h], __shfl_xor_sync(0xffffffffu, mn[h], o));
                mx[h] = fmaxf(mx[h], __shfl_xor_sync(0xffffffffu, mx[h], o));
            }
        }
        if ((tid & 31) == 0) {
            int w = tid >> 5;
#pragma unroll
            for (int h = 0; h < 8; h++) {
                sMn[w][h] = mn[h];
                sMx[w][h] = mx[h];
            }
        }
    }
    __syncthreads();
    float* sOut = &sP[0][0][0];
    if (tid < 64) {
#pragma unroll
        for (int h = 0; h < 8; h++) {
            float mnF = fminf(sMn[0][h], sMn[1][h]);
            float mxF = fmaxf(sMx[0][h], sMx[1][h]);
            float v = (t[h] - mnF) / (mxF - mnF + EPSV);
            sOut[tid * 8 + h] = fmaxf(v, 0.f);
        }
    }
    __syncthreads();
    ((float4*)(g_dataB + ((size_t)j << 9)))[tid] = ((const float4*)sOut)[tid];
}

// ---------------- layer 2: 128 thr x float4, unroll 8 ----------------
__global__ void k_layer2(const float* __restrict__ W) {
    int j = blockIdx.x, tid = threadIdx.x;
    int deg = g_cnt2[j];
    const int* __restrict__ row_ids = g_ell2 + j * MAXDEG;

    float4 acc = make_float4(0.f, 0.f, 0.f, 0.f);
    int k = 0;
    for (; k + 7 < deg; k += 8) {
        float4 v0 = ((const float4*)(g_dataB + ((size_t)row_ids[k] << 9)))[tid];
        float4 v1 = ((const float4*)(g_dataB + ((size_t)row_ids[k + 1] << 9)))[tid];
        float4 v2 = ((const float4*)(g_dataB + ((size_t)row_ids[k + 2] << 9)))[tid];
        float4 v3 = ((const float4*)(g_dataB + ((size_t)row_ids[k + 3] << 9)))[tid];
        float4 v4 = ((const float4*)(g_dataB + ((size_t)row_ids[k + 4] << 9)))[tid];
        float4 v5 = ((const float4*)(g_dataB + ((size_t)row_ids[k + 5] << 9)))[tid];
        float4 v6 = ((const float4*)(g_dataB + ((size_t)row_ids[k + 6] << 9)))[tid];
        float4 v7 = ((const float4*)(g_dataB + ((size_t)row_ids[k + 7] << 9)))[tid];
        acc.x += v0.x + v1.x + v2.x + v3.x + v4.x + v5.x + v6.x + v7.x;
        acc.y += v0.y + v1.y + v2.y + v3.y + v4.y + v5.y + v6.y + v7.y;
        acc.z += v0.z + v1.z + v2.z + v3.z + v4.z + v5.z + v6.z + v7.z;
        acc.w += v0.w + v1.w + v2.w + v3.w + v4.w + v5.w + v6.w + v7.w;
    }
    for (; k < deg; k++) {
        float4 v = ((const float4*)(g_dataB + ((size_t)row_ids[k] << 9)))[tid];
        acc.x += v.x; acc.y += v.y; acc.z += v.z; acc.w += v.w;
    }
    float inv = 1.f / (float)(deg > 0 ? deg : 1);
    acc.x *= inv; acc.y *= inv; acc.z *= inv; acc.w *= inv;

    __shared__ float sA[512];
    __shared__ float sW[64];
    __shared__ float sMn[2][8], sMx[2][8];
    ((float4*)sA)[tid] = acc;
    if (tid < 64) sW[tid] = W[tid];
    __syncthreads();

    float t[8];
    if (tid < 64) {
        float a[8];
#pragma unroll
        for (int d = 0; d < 8; d++) a[d] = sA[tid * 8 + d];
        float mn[8], mx[8];
#pragma unroll
        for (int h = 0; h < 8; h++) {
            float s = 0.f;
#pragma unroll
            for (int d = 0; d < 8; d++) s += a[d] * sW[h * 8 + d];
            t[h] = s;
            mn[h] = s;
            mx[h] = s;
        }
#pragma unroll
        for (int o = 16; o; o >>= 1) {
#pragma unroll
            for (int h = 0; h < 8; h++) {
                mn[h] = fminf(mn[h], __shfl_xor_sync(0xffffffffu, mn[h], o));
                mx[h] = fmaxf(mx[h], __shfl_xor_sync(0xffffffffu, mx[h], o));
            }
        }
        if ((tid & 31) == 0) {
            int w = tid >> 5;
#pragma unroll
            for (int h = 0; h < 8; h++) {
                sMn[w][h] = mn[h];
                sMx[w][h] = mx[h];
            }
        }
    }
    __syncthreads();
    if (tid < 64) {
#pragma unroll
        for (int h = 0; h < 8; h++) {
            float mnF = fminf(sMn[0][h], sMn[1][h]);
            float mxF = fmaxf(sMx[0][h], sMx[1][h]);
            float v = (t[h] - mnF) / (mxF - mnF + EPSV);
            sA[tid * 8 + h] = fmaxf(v, 0.f);
        }
    }
    __syncthreads();
    ((float4*)(g_dataC + ((size_t)j << 9)))[tid] = ((const float4*)sA)[tid];
}

// ---------------- final dot: out[b] = data3[b].flat . Wout + bout ----------------
__global__ void k_out(const float* __restrict__ Wout,
                      const float* __restrict__ bout, float* __restrict__ out) {
    int b = blockIdx.x, tid = threadIdx.x;  // 256 threads
    float acc = 0.f;
    for (int idx = tid; idx < M2 * HH; idx += 256) {
        int j = idx >> 3, h = idx & 7;
        acc += g_dataC[((size_t)j << 9) + b * 8 + h] * Wout[idx];
    }
    __shared__ float s[256];
    s[tid] = acc;
    __syncthreads();
    for (int o = 128; o; o >>= 1) {
        if (tid < o) s[tid] += s[tid + o];
        __syncthreads();
    }
    if (tid == 0) out[b] = s[0] + bout[0];
}

// ---------------- host ----------------
extern "C" void kernel_launch(void* const* d_in, const int* in_sizes, int n_in,
                              void* d_out, int out_size) {
    const float *x = 0, *W0 = 0, *W1 = 0, *W2 = 0, *Wout = 0, *bout = 0;
    const int *s0 = 0, *d0 = 0, *s1 = 0, *d1 = 0, *s2 = 0, *d2 = 0;
    for (int i = 0; i < n_in; i++) {
        int sz = in_sizes[i];
        const void* p = d_in[i];
        if (sz == BB * N0) x = (const float*)p;
        else if (sz == E0) { if (!s0) s0 = (const int*)p; else d0 = (const int*)p; }
        else if (sz == E1) { if (!s1) s1 = (const int*)p; else d1 = (const int*)p; }
        else if (sz == E2) { if (!s2) s2 = (const int*)p; else d2 = (const int*)p; }
        else if (sz == HH) W0 = (const float*)p;
        else if (sz == HH * HH) { if (!W1) W1 = (const float*)p; else W2 = (const float*)p; }
        else if (sz == M2 * HH) Wout = (const float*)p;
        else if (sz == 1) bout = (const float*)p;
    }
    float* out = (float*)d_out;

    k_zero_all<<<42, 256>>>();
    k_prep<<<TP_BLOCKS + EB + 1, 256>>>(x, s0, d0, s1, d1, s2, d2);
    k_layer0<<<M0, 256>>>(W0);
    k_layer1<<<M1, 128>>>(W1);
    k_layer2<<<M2, 128>>>(W2);
    k_out<<<BB, 256>>>(Wout, bout, out);
}

// round 11
// speedup vs baseline: 2.5077x; 1.6117x over previous
#include <cuda_runtime.h>
#include <cuda_fp16.h>

#define N0 20000
#define E0 200000
#define M0 8000
#define E1 80000
#define M1 2000
#define E2 20000
#define M2 500
#define BB 64
#define HH 8
#define EPSV 1e-8f

#define ETOT (E0 + E1 + E2)
#define TP_BLOCKS 1250  /* (20000/32) * (64/32) transpose tiles */
#define EB ((ETOT + 255) / 256)  /* one-edge-per-thread blocks */
#define MAXDEG 96

// ---------------- device scratch (no allocs allowed) ----------------
__device__ __half g_xTh[N0 * BB];           // x transposed, fp16: [node][b]
__device__ __half g_dataAh[M0 * BB * HH];   // layer-0 output, fp16
__device__ __half g_dataBh[M1 * BB * HH];   // layer-1 output, fp16
__device__ float g_dataC[M2 * BB * HH];     // layer-2 output, fp32
__device__ int g_cnt0[M0], g_cnt1[M1], g_cnt2[M2];
__device__ int g_ell0[M0 * MAXDEG];
__device__ int g_ell1[M1 * MAXDEG];
__device__ int g_ell2[M2 * MAXDEG];

__device__ __forceinline__ void acc8_from_uint4(float* acc, uint4 v) {
    float2 f0 = __half22float2(*(__half2*)&v.x);
    float2 f1 = __half22float2(*(__half2*)&v.y);
    float2 f2 = __half22float2(*(__half2*)&v.z);
    float2 f3 = __half22float2(*(__half2*)&v.w);
    acc[0] += f0.x; acc[1] += f0.y; acc[2] += f1.x; acc[3] += f1.y;
    acc[4] += f2.x; acc[5] += f2.y; acc[6] += f3.x; acc[7] += f3.y;
}

// ---------------- zero all three count arrays ----------------
__global__ void k_zero_all() {
    int i = blockIdx.x * blockDim.x + threadIdx.x;
    int st = gridDim.x * blockDim.x;
    for (int k = i; k < M0; k += st) g_cnt0[k] = 0;
    for (int k = i; k < M1; k += st) g_cnt1[k] = 0;
    for (int k = i; k < M2; k += st) g_cnt2[k] = 0;
}

// ---------------- fused: transpose x (fp32->fp16) + one-pass ELL fill ----------------
__global__ void k_prep(const float* __restrict__ x,
                       const int* __restrict__ s0, const int* __restrict__ d0,
                       const int* __restrict__ s1, const int* __restrict__ d1,
                       const int* __restrict__ s2, const int* __restrict__ d2) {
    int b = blockIdx.x;
    int tid = threadIdx.x;
    if (b < TP_BLOCKS) {
        __shared__ float tile[32][33];
        int bx = b % 625, by = b / 625;
        int n0 = bx * 32, b0 = by * 32;
        int tx = tid & 31, ty0 = tid >> 5;
#pragma unroll
        for (int i = 0; i < 32; i += 8) {
            int ty = ty0 + i;
            tile[ty][tx] = x[(size_t)(b0 + ty) * N0 + (n0 + tx)];
        }
        __syncthreads();
#pragma unroll
        for (int i = 0; i < 32; i += 8) {
            int ty = ty0 + i;
            g_xTh[(size_t)(n0 + ty) * BB + (b0 + tx)] =
                __float2half(tile[tx][ty]);
        }
    } else {
        // one edge per thread: load dst, grab slot, scatter src
        int i = (b - TP_BLOCKS) * 256 + tid;
        if (i < E0) {
            int d = d0[i];
            int slot = atomicAdd(&g_cnt0[d], 1);
            g_ell0[d * MAXDEG + slot] = s0[i];
        } else if (i < E0 + E1) {
            int j = i - E0;
            int d = d1[j];
            int slot = atomicAdd(&g_cnt1[d], 1);
            g_ell1[d * MAXDEG + slot] = s1[j];
        } else if (i < ETOT) {
            int j = i - E0 - E1;
            int d = d2[j];
            int slot = atomicAdd(&g_cnt2[d], 1);
            g_ell2[d * MAXDEG + slot] = s2[j];
        }
    }
}

// ---------------- layer 0: warp-per-node, barrier-free ----------------
// grid = M0/8 blocks x 256 thr. Warp = 1 node: 4 edge-subgroups x 8 lanes.
// Uses identity: min_b(a*W0h) = W0h>=0 ? W0h*min(a) : W0h*max(a)  (exact,
// monotone rounding), so minmax needs only scalar min/max of a over b.
__global__ void k_layer0(const float* __restrict__ W0) {
    int warp = threadIdx.x >> 5;
    int lane = threadIdx.x & 31;
    int j = blockIdx.x * 8 + warp;
    int sg = lane >> 3, li = lane & 7;  // sg: edge subgroup, li: 16B chunk
    int deg = g_cnt0[j];
    const int* __restrict__ row_ids = g_ell0 + j * MAXDEG;

    float acc[8];
#pragma unroll
    for (int i = 0; i < 8; i++) acc[i] = 0.f;
    for (int k = sg; k < deg; k += 4) {
        const uint4* row = (const uint4*)(g_xTh + ((size_t)row_ids[k] << 6));
        acc8_from_uint4(acc, row[li]);
    }
    // reduce over the 4 subgroups (lanes same li): all lanes end with full sum
#pragma unroll
    for (int i = 0; i < 8; i++) {
        acc[i] += __shfl_xor_sync(0xffffffffu, acc[i], 8);
        acc[i] += __shfl_xor_sync(0xffffffffu, acc[i], 16);
    }
    float inv = 1.f / (float)(deg > 0 ? deg : 1);
    float amn = acc[0] * inv, amx = amn;
#pragma unroll
    for (int i = 0; i < 8; i++) {
        float a = acc[i] * inv;
        amn = fminf(amn, a);
        amx = fmaxf(amx, a);
    }
#pragma unroll
    for (int o = 16; o; o >>= 1) {
        amn = fminf(amn, __shfl_xor_sync(0xffffffffu, amn, o));
        amx = fmaxf(amx, __shfl_xor_sync(0xffffffffu, amx, o));
    }

    // stage a[b] to shared (per-warp slice), redistribute for coalesced store
    __shared__ float sAgg[8][64];
    if (sg == 0) {
#pragma unroll
        for (int i = 0; i < 8; i++) sAgg[warp][li * 8 + i] = acc[i] * inv;
    }
    __syncwarp();
    float a0 = sAgg[warp][lane * 2];
    float a1 = sAgg[warp][lane * 2 + 1];

    // each lane: b = lane*2, lane*2+1; 16 halfs = 32B contiguous
    uint4 st0, st1;
    unsigned* p0 = (unsigned*)&st0;
    unsigned* p1 = (unsigned*)&st1;
#pragma unroll
    for (int hp = 0; hp < 4; hp++) {
        float w0 = W0[hp * 2], w1 = W0[hp * 2 + 1];
        float mn0 = w0 >= 0.f ? w0 * amn : w0 * amx;
        float mx0 = w0 >= 0.f ? w0 * amx : w0 * amn;
        float mn1 = w1 >= 0.f ? w1 * amn : w1 * amx;
        float mx1 = w1 >= 0.f ? w1 * amx : w1 * amn;
        float id0 = 1.f / (mx0 - mn0 + EPSV);
        float id1 = 1.f / (mx1 - mn1 + EPSV);
        float v0a = fmaxf((a0 * w0 - mn0) * id0, 0.f);
        float v1a = fmaxf((a0 * w1 - mn1) * id1, 0.f);
        float v0b = fmaxf((a1 * w0 - mn0) * id0, 0.f);
        float v1b = fmaxf((a1 * w1 - mn1) * id1, 0.f);
        __half2 ha = __floats2half2_rn(v0a, v1a);
        __half2 hb = __floats2half2_rn(v0b, v1b);
        p0[hp] = *(unsigned*)&ha;
        p1[hp] = *(unsigned*)&hb;
    }
    uint4* dst = (uint4*)(g_dataAh + ((size_t)j << 9));
    dst[lane * 2] = st0;
    dst[lane * 2 + 1] = st1;
}

// ---------------- layer 1: 128 thr; 64 lanes(uint4) x 2 groups -> fp16 dataB ----------------
__global__ void k_layer1(const float* __restrict__ W) {
    int j = blockIdx.x, tid = threadIdx.x;
    int lane = tid & 63, grp = tid >> 6;
    int deg = g_cnt1[j];
    const int* __restrict__ row_ids = g_ell1 + j * MAXDEG;

    float acc[8];
#pragma unroll
    for (int i = 0; i < 8; i++) acc[i] = 0.f;
    int k = grp;
    for (; k + 6 < deg; k += 8) {
        uint4 v0 = ((const uint4*)(g_dataAh + ((size_t)row_ids[k] << 9)))[lane];
        uint4 v1 = ((const uint4*)(g_dataAh + ((size_t)row_ids[k + 2] << 9)))[lane];
        uint4 v2 = ((const uint4*)(g_dataAh + ((size_t)row_ids[k + 4] << 9)))[lane];
        uint4 v3 = ((const uint4*)(g_dataAh + ((size_t)row_ids[k + 6] << 9)))[lane];
        acc8_from_uint4(acc, v0);
        acc8_from_uint4(acc, v1);
        acc8_from_uint4(acc, v2);
        acc8_from_uint4(acc, v3);
    }
    for (; k < deg; k += 2) {
        uint4 v = ((const uint4*)(g_dataAh + ((size_t)row_ids[k] << 9)))[lane];
        acc8_from_uint4(acc, v);
    }

    __shared__ float sP[2][64][8];  // [group][b][h]
    __shared__ float sW[64];
    __shared__ float sMn[2][8], sMx[2][8];
#pragma unroll
    for (int i = 0; i < 8; i++) sP[grp][lane][i] = acc[i];
    if (tid < 64) sW[tid] = W[tid];
    __syncthreads();

    float t[8];
    if (tid < 64) {
        float inv = 1.f / (float)(deg > 0 ? deg : 1);
        float a[8];
#pragma unroll
        for (int d = 0; d < 8; d++)
            a[d] = (sP[0][tid][d] + sP[1][tid][d]) * inv;
        float mn[8], mx[8];
#pragma unroll
        for (int h = 0; h < 8; h++) {
            float s = 0.f;
#pragma unroll
            for (int d = 0; d < 8; d++) s += a[d] * sW[h * 8 + d];
            t[h] = s;
            mn[h] = s;
            mx[h] = s;
        }
#pragma unroll
        for (int o = 16; o; o >>= 1) {
#pragma unroll
            for (int h = 0; h < 8; h++) {
                mn[h] = fminf(mn[h], __shfl_xor_sync(0xffffffffu, mn[h], o));
                mx[h] = fmaxf(mx[h], __shfl_xor_sync(0xffffffffu, mx[h], o));
            }
        }
        if ((tid & 31) == 0) {
            int w = tid >> 5;
#pragma unroll
            for (int h = 0; h < 8; h++) {
                sMn[w][h] = mn[h];
                sMx[w][h] = mx[h];
            }
        }
    }
    __syncthreads();
    float* sOut = &sP[0][0][0];
    if (tid < 64) {
#pragma unroll
        for (int h = 0; h < 8; h++) {
            float mnF = fminf(sMn[0][h], sMn[1][h]);
            float mxF = fmaxf(sMx[0][h], sMx[1][h]);
            float v = (t[h] - mnF) / (mxF - mnF + EPSV);
            sOut[tid * 8 + h] = fmaxf(v, 0.f);
        }
    }
    __syncthreads();
    // store 512 halfs: 128 thr x uint2
    {
        float4 o = ((const float4*)sOut)[tid];
        __half2 h0 = __floats2half2_rn(o.x, o.y);
        __half2 h1 = __floats2half2_rn(o.z, o.w);
        uint2 st;
        st.x = *(unsigned*)&h0;
        st.y = *(unsigned*)&h1;
        ((uint2*)(g_dataBh + ((size_t)j << 9)))[tid] = st;
    }
}

// ---------------- layer 2: 256 thr; 64 lanes(uint4) x 4 groups, fp16 in -> fp32 out ----------------
__global__ void k_layer2(const float* __restrict__ W) {
    int j = blockIdx.x, tid = threadIdx.x;
    int lane = tid & 63, grp = tid >> 6;  // 4 groups
    int deg = g_cnt2[j];
    const int* __restrict__ row_ids = g_ell2 + j * MAXDEG;

    float acc[8];
#pragma unroll
    for (int i = 0; i < 8; i++) acc[i] = 0.f;
    int k = grp;
    for (; k + 12 < deg; k += 16) {
        uint4 v0 = ((const uint4*)(g_dataBh + ((size_t)row_ids[k] << 9)))[lane];
        uint4 v1 = ((const uint4*)(g_dataBh + ((size_t)row_ids[k + 4] << 9)))[lane];
        uint4 v2 = ((const uint4*)(g_dataBh + ((size_t)row_ids[k + 8] << 9)))[lane];
        uint4 v3 = ((const uint4*)(g_dataBh + ((size_t)row_ids[k + 12] << 9)))[lane];
        acc8_from_uint4(acc, v0);
        acc8_from_uint4(acc, v1);
        acc8_from_uint4(acc, v2);
        acc8_from_uint4(acc, v3);
    }
    for (; k < deg; k += 4) {
        uint4 v = ((const uint4*)(g_dataBh + ((size_t)row_ids[k] << 9)))[lane];
        acc8_from_uint4(acc, v);
    }

    __shared__ float sP[4][64][8];  // [group][b][h]
    __shared__ float sW[64];
    __shared__ float sMn[2][8], sMx[2][8];
#pragma unroll
    for (int i = 0; i < 8; i++) sP[grp][lane][i] = acc[i];
    if (tid < 64) sW[tid] = W[tid];
    __syncthreads();

    float t[8];
    if (tid < 64) {
        float inv = 1.f / (float)(deg > 0 ? deg : 1);
        float a[8];
#pragma unroll
        for (int d = 0; d < 8; d++)
            a[d] = (sP[0][tid][d] + sP[1][tid][d] + sP[2][tid][d] +
                    sP[3][tid][d]) * inv;
        float mn[8], mx[8];
#pragma unroll
        for (int h = 0; h < 8; h++) {
            float s = 0.f;
#pragma unroll
            for (int d = 0; d < 8; d++) s += a[d] * sW[h * 8 + d];
            t[h] = s;
            mn[h] = s;
            mx[h] = s;
        }
#pragma unroll
        for (int o = 16; o; o >>= 1) {
#pragma unroll
            for (int h = 0; h < 8; h++) {
                mn[h] = fminf(mn[h], __shfl_xor_sync(0xffffffffu, mn[h], o));
                mx[h] = fmaxf(mx[h], __shfl_xor_sync(0xffffffffu, mx[h], o));
            }
        }
        if ((tid & 31) == 0) {
            int w = tid >> 5;
#pragma unroll
            for (int h = 0; h < 8; h++) {
                sMn[w][h] = mn[h];
                sMx[w][h] = mx[h];
            }
        }
    }
    __syncthreads();
    if (tid < 64) {
#pragma unroll
        for (int h = 0; h < 8; h++) {
            float mnF = fminf(sMn[0][h], sMn[1][h]);
            float mxF = fmaxf(sMx[0][h], sMx[1][h]);
            float v = (t[h] - mnF) / (mxF - mnF + EPSV);
            g_dataC[((size_t)j << 9) + tid * 8 + h] = fmaxf(v, 0.f);
        }
    }
}

// ---------------- final dot: out[b] = data3[b].flat . Wout + bout ----------------
__global__ void k_out(const float* __restrict__ Wout,
                      const float* __restrict__ bout, float* __restrict__ out) {
    int b = blockIdx.x, tid = threadIdx.x;  // 256 threads
    float acc = 0.f;
    for (int idx = tid; idx < M2 * HH; idx += 256) {
        int j = idx >> 3, h = idx & 7;
        acc += g_dataC[((size_t)j << 9) + b * 8 + h] * Wout[idx];
    }
    __shared__ float s[256];
    s[tid] = acc;
    __syncthreads();
    for (int o = 128; o; o >>= 1) {
        if (tid < o) s[tid] += s[tid + o];
        __syncthreads();
    }
    if (tid == 0) out[b] = s[0] + bout[0];
}

// ---------------- host ----------------
extern "C" void kernel_launch(void* const* d_in, const int* in_sizes, int n_in,
                              void* d_out, int out_size) {
    const float *x = 0, *W0 = 0, *W1 = 0, *W2 = 0, *Wout = 0, *bout = 0;
    const int *s0 = 0, *d0 = 0, *s1 = 0, *d1 = 0, *s2 = 0, *d2 = 0;
    for (int i = 0; i < n_in; i++) {
        int sz = in_sizes[i];
        const void* p = d_in[i];
        if (sz == BB * N0) x = (const float*)p;
        else if (sz == E0) { if (!s0) s0 = (const int*)p; else d0 = (const int*)p; }
        else if (sz == E1) { if (!s1) s1 = (const int*)p; else d1 = (const int*)p; }
        else if (sz == E2) { if (!s2) s2 = (const int*)p; else d2 = (const int*)p; }
        else if (sz == HH) W0 = (const float*)p;
        else if (sz == HH * HH) { if (!W1) W1 = (const float*)p; else W2 = (const float*)p; }
        else if (sz == M2 * HH) Wout = (const float*)p;
        else if (sz == 1) bout = (const float*)p;
    }
    float* out = (float*)d_out;

    k_zero_all<<<42, 256>>>();
    k_prep<<<TP_BLOCKS + EB + 1, 256>>>(x, s0, d0, s1, d1, s2, d2);
    k_layer0<<<M0 / 8, 256>>>(W0);
    k_layer1<<<M1, 128>>>(W1);
    k_layer2<<<M2, 256>>>(W2);
    k_out<<<BB, 256>>>(Wout, bout, out);
}